// round 5
// baseline (speedup 1.0000x reference)
#include <cuda_runtime.h>
#include <cuda_bf16.h>

#define JT    64     // j-tile width
#define IT    256    // i-tile height (2 rows per thread)
#define NTHR  128
#define MAXB  8192
#define SENT  (-3.0e38f)

__device__ double        g_partials[MAXB];
__device__ unsigned int  g_ticket = 0;

typedef unsigned long long u64;

__device__ __forceinline__ u64 pack2(float lo, float hi) {
    u64 r; asm("mov.b64 %0, {%1, %2};" : "=l"(r) : "f"(lo), "f"(hi)); return r;
}
__device__ __forceinline__ void unpack2(u64 v, float& lo, float& hi) {
    asm("mov.b64 {%0, %1}, %2;" : "=f"(lo), "=f"(hi) : "l"(v));
}
__device__ __forceinline__ u64 add2(u64 a, u64 b) {
    u64 r; asm("add.rn.f32x2 %0, %1, %2;" : "=l"(r) : "l"(a), "l"(b)); return r;
}

// Exact per-pair loss (slow path): t1 = 0.2s - d, t2 = d - s, u = -d.
__device__ __forceinline__ float sel_loss(float t1, float t2, float u) {
    float mm = fmaxf(t1, t2);
    float s  = (u > 0.0f) ? u : mm;
    return fmaxf(s, 0.0f);
}

__global__ void __launch_bounds__(NTHR, 8)
dl_fused_kernel(const float* __restrict__ p,
                const float* __restrict__ z_spacing,
                const float* __restrict__ nth_slice,
                float* __restrict__ out,
                int n, int nblocks) {
    __shared__ float4 qxy[JT / 2];   // (x_{2k}, y_{2k}, x_{2k+1}, y_{2k+1})  (slow path)
    __shared__ float2 qz [JT / 2];   // (pj_{2k}, pj_{2k+1})                  (both paths)
    __shared__ double wsum[NTHR / 32];
    __shared__ float  red_max[NTHR / 32], red_min[NTHR / 32], red_sum[NTHR / 32];
    __shared__ bool   is_last;

    const int tid = threadIdx.x;

    // Decode (ti, tj): per-ti block count = 4*ti + 4, start(ti) = 2*ti*(ti+1).
    int t  = blockIdx.x;
    int ti = (int)((sqrtf(2.0f * (float)t + 1.0f) - 1.0f) * 0.5f);
    while (2 * (ti + 1) * (ti + 2) <= t) ti++;
    while (2 * ti * (ti + 1) > t) ti--;
    const int tj = t - 2 * ti * (ti + 1);

    const float step = z_spacing[0] * nth_slice[0];   // STEP == 1.0
    const float c02  = 0.2f * step;

    const int gj0 = tj * JT;
    const int gi0 = ti * IT + tid;        // row A
    const int gi1 = gi0 + NTHR;           // row B

    // Stage j-tile.
    if (tid < JT / 2) {
        int j0 = gj0 + 2 * tid, j1 = j0 + 1;
        float x0, y0, z0, x1, y1, z1;
        if (j0 < n) {
            float pv = p[j0], jf = (float)j0;
            x0 = pv - c02 * jf; y0 = step * jf - pv; z0 = pv;
        } else { x0 = y0 = z0 = SENT; }
        if (j1 < n) {
            float pv = p[j1], jf = (float)j1;
            x1 = pv - c02 * jf; y1 = step * jf - pv; z1 = pv;
        } else { x1 = y1 = z1 = SENT; }
        qxy[tid] = make_float4(x0, y0, x1, y1);
        qz [tid] = make_float2(z0, z1);
    }

    const bool  v0 = (gi0 < n), v1 = (gi1 < n);
    const float pi0 = v0 ? p[gi0] : 0.0f;
    const float pi1 = v1 ? p[gi1] : 0.0f;

    __syncthreads();

    // Block reduction of (pImax over i-rows, pJmin over j-tile, Sp = sum pj).
    {
        float lmax = fmaxf(v0 ? pi0 : SENT, v1 ? pi1 : SENT);
        float pjv  = (tid < JT) ? ((const float*)qz)[tid] : 0.0f;
        float lmin = (tid < JT) ? pjv : 3.0e38f;
        float lsum = (tid < JT) ? pjv : 0.0f;
        #pragma unroll
        for (int off = 16; off > 0; off >>= 1) {
            lmax = fmaxf(lmax, __shfl_down_sync(0xffffffffu, lmax, off));
            lmin = fminf(lmin, __shfl_down_sync(0xffffffffu, lmin, off));
            lsum += __shfl_down_sync(0xffffffffu, lsum, off);
        }
        if ((tid & 31) == 0) {
            red_max[tid >> 5] = lmax; red_min[tid >> 5] = lmin; red_sum[tid >> 5] = lsum;
        }
    }
    __syncthreads();
    const float pImax = fmaxf(fmaxf(red_max[0], red_max[1]), fmaxf(red_max[2], red_max[3]));
    const float pJmin = fminf(fminf(red_min[0], red_min[1]), fminf(red_min[2], red_min[3]));
    const float Sp    = (red_sum[0] + red_sum[1]) + (red_sum[2] + red_sum[3]);

    // Fast-tile classification: full tile, strictly below diagonal, and
    // every d>=0 pair satisfies d < 0.2*steps (with 1% safety margin).
    const int  dmin = ti * IT - (gj0 + JT - 1);
    const bool fast = (gj0 + JT <= n) && v1 && (dmin > 0) &&
                      ((pImax - pJmin) < 0.99f * c02 * (float)dmin);

    double v;

    if (fast) {
        // loss(i,j) = c02*(i-j)*[pj <= pi] - (pi - pj)
        // Per row: c02*(d0*C - SJ) - (JT*pi - Sp), with C, SJ exact ints.
        int C0 = 0, S0 = 0, C1 = 0, S1 = 0;
        #pragma unroll 8
        for (int k = 0; k < JT; k += 2) {
            float2 pj2 = qz[k >> 1];
            if (pj2.x <= pi0) { C0++; S0 += k;     }
            if (pj2.y <= pi0) { C0++; S0 += k + 1; }
            if (pj2.x <= pi1) { C1++; S1 += k;     }
            if (pj2.y <= pi1) { C1++; S1 += k + 1; }
        }
        const int d00 = gi0 - gj0, d01 = gi1 - gj0;
        float fa = c02 * (float)(d00 * C0 - S0) - ((float)JT * pi0 - Sp);
        float fb = c02 * (float)(d01 * C1 - S1) - ((float)JT * pi1 - Sp);
        v = (double)fa + (double)fb;
    } else {
        // Slow path: exact reference op sequence (R3 code).
        const u64 P12_0 = pack2(c02 * (float)gi0 - pi0, pi0 - step * (float)gi0);
        const u64 P12_1 = pack2(c02 * (float)gi1 - pi1, pi1 - step * (float)gi1);
        const u64 NPI0  = pack2(-pi0, -pi0);
        const u64 NPI1  = pack2(-pi1, -pi1);
        int rel0 = v0 ? (gi0 - gj0) : -1;
        int rel1 = v1 ? (gi1 - gj0) : -1;

        float a0 = 0.0f, a1 = 0.0f, b0 = 0.0f, b1 = 0.0f;
        const float* qxf = (const float*)qxy;
        const float* qzf = (const float*)qz;

        if (rel0 >= JT - 1) {
            #pragma unroll 8
            for (int k = 0; k < JT / 2; ++k) {
                float4 xy = qxy[k]; float2 zz = qz[k];
                u64 tA = add2(P12_0, pack2(xy.x, xy.y));
                u64 tB = add2(P12_0, pack2(xy.z, xy.w));
                u64 uu = add2(pack2(zz.x, zz.y), NPI0);
                float t1, t2, t3, t4, u0c, u1c;
                unpack2(tA, t1, t2); unpack2(tB, t3, t4); unpack2(uu, u0c, u1c);
                a0 += sel_loss(t1, t2, u0c);
                a1 += sel_loss(t3, t4, u1c);
            }
        } else if (rel0 >= 0) {
            for (int jj = 0; jj <= rel0 && gj0 + jj < n; ++jj) {
                int idx = ((jj >> 1) << 2) | ((jj & 1) << 1);
                float t1 = (c02 * (float)gi0 - pi0) + qxf[idx];
                float t2 = (pi0 - step * (float)gi0) + qxf[idx + 1];
                float u  = qzf[jj] - pi0;
                a0 += sel_loss(t1, t2, u);
            }
        }
        if (rel1 >= JT - 1) {
            #pragma unroll 8
            for (int k = 0; k < JT / 2; ++k) {
                float4 xy = qxy[k]; float2 zz = qz[k];
                u64 tA = add2(P12_1, pack2(xy.x, xy.y));
                u64 tB = add2(P12_1, pack2(xy.z, xy.w));
                u64 uu = add2(pack2(zz.x, zz.y), NPI1);
                float t1, t2, t3, t4, u0c, u1c;
                unpack2(tA, t1, t2); unpack2(tB, t3, t4); unpack2(uu, u0c, u1c);
                b0 += sel_loss(t1, t2, u0c);
                b1 += sel_loss(t3, t4, u1c);
            }
        } else if (rel1 >= 0) {
            for (int jj = 0; jj <= rel1 && gj0 + jj < n; ++jj) {
                int idx = ((jj >> 1) << 2) | ((jj & 1) << 1);
                float t1 = (c02 * (float)gi1 - pi1) + qxf[idx];
                float t2 = (pi1 - step * (float)gi1) + qxf[idx + 1];
                float u  = qzf[jj] - pi1;
                b0 += sel_loss(t1, t2, u);
            }
        }
        v = (double)((a0 + a1) + (b0 + b1));
    }

    // Block reduction in double.
    #pragma unroll
    for (int off = 16; off > 0; off >>= 1)
        v += __shfl_down_sync(0xffffffffu, v, off);
    if ((tid & 31) == 0) wsum[tid >> 5] = v;
    __syncthreads();
    if (tid < 32) {
        v = (tid < (NTHR / 32)) ? wsum[tid] : 0.0;
        #pragma unroll
        for (int off = 2; off > 0; off >>= 1)
            v += __shfl_down_sync(0xffffffffu, v, off);
        if (tid == 0) {
            g_partials[blockIdx.x] = v;
            __threadfence();
            unsigned int ticket = atomicAdd(&g_ticket, 1u);
            is_last = (ticket == (unsigned int)(nblocks - 1));
        }
    }
    __syncthreads();

    // Last block reduces all partials, writes output, resets ticket.
    if (is_last) {
        __threadfence();
        double s = 0.0;
        for (int i = tid; i < nblocks; i += NTHR)
            s += g_partials[i];
        #pragma unroll
        for (int off = 16; off > 0; off >>= 1)
            s += __shfl_down_sync(0xffffffffu, s, off);
        if ((tid & 31) == 0) wsum[tid >> 5] = s;
        __syncthreads();
        if (tid == 0) {
            double tot = 0.0;
            #pragma unroll
            for (int w = 0; w < NTHR / 32; ++w) tot += wsum[w];
            double nn = (double)n * (double)n;
            out[0] = (float)(tot / nn);
            g_ticket = 0;   // reset for next graph replay
        }
    }
}

extern "C" void kernel_launch(void* const* d_in, const int* in_sizes, int n_in,
                              void* d_out, int out_size) {
    const float* p   = (const float*)d_in[0];
    const float* z   = (const float*)d_in[1];
    const float* nth = (const float*)d_in[2];
    float* out = (float*)d_out;
    int n = in_sizes[0];

    int nti = (n + IT - 1) / IT;
    int nblocks = 2 * nti * (nti + 1);
    if (nblocks > MAXB) nblocks = MAXB;   // n = 8192 -> 2112

    dl_fused_kernel<<<nblocks, NTHR>>>(p, z, nth, out, n, nblocks);
}